// round 4
// baseline (speedup 1.0000x reference)
#include <cuda_runtime.h>
#include <cstdint>

#define BB 4
#define SS 1024
#define HH 1024
#define NHEADS 16
#define DKH 64

// Scratch: q-projection, k-projection, attention output (pre final GEMM)
__device__ float g_q[BB * SS * HH];
__device__ float g_k[BB * SS * HH];
__device__ float g_attn[BB * SS * HH];

__device__ __forceinline__ float f4get(const float4& v, int t) {
    switch (t) { case 0: return v.x; case 1: return v.y; case 2: return v.z; default: return v.w; }
}

// ---------------------------------------------------------------------------
// C[M,N] = A[M,K] @ W[K,N] + bias[N]   (fp32, 64x64 tile, BK=16, 4x4 microtile)
// ---------------------------------------------------------------------------
__global__ __launch_bounds__(256) void sgemm_bias_kernel(
    const float* __restrict__ A, const float* __restrict__ W,
    const float* __restrict__ bias, float* __restrict__ C,
    int M, int N, int K)
{
    __shared__ float As[16][64];   // [k][m]
    __shared__ float Ws[16][64];   // [k][n]
    const int tid = threadIdx.x;
    const int tx = tid & 15, ty = tid >> 4;
    const int m0 = blockIdx.y * 64, n0 = blockIdx.x * 64;
    const int arow = tid >> 2, acol = (tid & 3) << 2;
    const int wrow = tid >> 4, wcol = (tid & 15) << 2;
    const float* Ap = A + (size_t)(m0 + arow) * K + acol;
    const float* Wp = W + (size_t)wrow * N + n0 + wcol;
    float acc[4][4] = {};

    for (int k0 = 0; k0 < K; k0 += 16) {
        float4 av = *(const float4*)(Ap + k0);
        As[acol + 0][arow] = av.x;
        As[acol + 1][arow] = av.y;
        As[acol + 2][arow] = av.z;
        As[acol + 3][arow] = av.w;
        *(float4*)&Ws[wrow][wcol] = *(const float4*)(Wp + (size_t)k0 * N);
        __syncthreads();
        #pragma unroll
        for (int k = 0; k < 16; k++) {
            float4 a4 = *(const float4*)&As[k][ty << 2];
            float4 b4 = *(const float4*)&Ws[k][tx << 2];
            float a[4] = {a4.x, a4.y, a4.z, a4.w};
            float b[4] = {b4.x, b4.y, b4.z, b4.w};
            #pragma unroll
            for (int i = 0; i < 4; i++)
                #pragma unroll
                for (int j = 0; j < 4; j++)
                    acc[i][j] += a[i] * b[j];
        }
        __syncthreads();
    }

    float4 bv = *(const float4*)(bias + n0 + (tx << 2));
    float bb[4] = {bv.x, bv.y, bv.z, bv.w};
    #pragma unroll
    for (int i = 0; i < 4; i++) {
        int r = m0 + (ty << 2) + i;
        float4 o;
        o.x = acc[i][0] + bb[0];
        o.y = acc[i][1] + bb[1];
        o.z = acc[i][2] + bb[2];
        o.w = acc[i][3] + bb[3];
        *(float4*)&C[(size_t)r * N + n0 + (tx << 2)] = o;
    }
}

// ---------------------------------------------------------------------------
// Fused attention: per (b, h, 64-row q tile); streams 32-row K/V tiles with
// online softmax. V = q-projection (reference uses q as value). Mask is int32
// (harness converts bool -> int32): nonzero = masked (-1e9); row_keep
// multiplies whole row by !mask[b,row,0].
// Static shared only (42.75 KB) -> no cudaFuncSetAttribute needed.
// ---------------------------------------------------------------------------
#define KT 32
#define SPAD 36

__global__ __launch_bounds__(256) void attn_kernel(
    const float* __restrict__ qp, const float* __restrict__ kp,
    const int* __restrict__ mask, float* __restrict__ out)
{
    __shared__ float sQ[64 * 64];     // q rows (row-major, d inner)
    __shared__ float sKt[64 * KT];    // K transposed: [d][kv_col]
    __shared__ float sV[KT * 64];     // V rows (= q-projection rows)
    __shared__ float sS[64 * SPAD];   // score / prob tile
    __shared__ float sMx[64];         // row running max
    __shared__ float sL[64];          // row running sum
    __shared__ float sC[64];          // row rescale factor this iter

    const int tid = threadIdx.x;
    const int tx = tid & 15, ty = tid >> 4;
    const int b = blockIdx.z, h = blockIdx.y;
    const int m0 = blockIdx.x * 64;

    // Load Q tile once: 64x64, 16 floats/thread
    {
        const int lr = tid >> 2;
        const int ld0 = (tid & 3) << 4;
        const float* src = qp + (size_t)(b * SS + m0 + lr) * HH + h * DKH + ld0;
        #pragma unroll
        for (int i = 0; i < 4; i++)
            *(float4*)&sQ[lr * 64 + ld0 + 4 * i] = *(const float4*)(src + 4 * i);
    }
    if (tid < 64) { sMx[tid] = -1e30f; sL[tid] = 0.f; }

    float acc[4][4] = {};

    const int lr2 = tid >> 3;         // 0..31 kv row for loads
    const int ld2 = (tid & 7) << 3;   // d offset (8 floats per thread)
    const int r0 = (tid >> 3) << 1;   // S rows: r0, r0+1
    const int c0 = (tid & 7) << 2;    // S cols: c0..c0+3

    for (int n0 = 0; n0 < SS; n0 += KT) {
        __syncthreads();   // previous PV done before K/V overwrite (also covers Q/init)
        // Load K tile transposed + V tile (V rows come from q-projection)
        {
            const float* ksrc = kp + (size_t)(b * SS + n0 + lr2) * HH + h * DKH + ld2;
            const float* vsrc = qp + (size_t)(b * SS + n0 + lr2) * HH + h * DKH + ld2;
            #pragma unroll
            for (int i = 0; i < 2; i++) {
                float4 kv = *(const float4*)(ksrc + 4 * i);
                int d = ld2 + 4 * i;
                sKt[(d + 0) * KT + lr2] = kv.x;
                sKt[(d + 1) * KT + lr2] = kv.y;
                sKt[(d + 2) * KT + lr2] = kv.z;
                sKt[(d + 3) * KT + lr2] = kv.w;
                *(float4*)&sV[lr2 * 64 + d] = *(const float4*)(vsrc + 4 * i);
            }
        }
        __syncthreads();

        // S = Q @ K^T for this tile (2x4 per thread over 64-deep k)
        float accS[2][4] = {};
        #pragma unroll
        for (int d0 = 0; d0 < 64; d0 += 4) {
            float4 aq[2];
            aq[0] = *(const float4*)&sQ[(r0 + 0) * 64 + d0];
            aq[1] = *(const float4*)&sQ[(r0 + 1) * 64 + d0];
            #pragma unroll
            for (int t = 0; t < 4; t++) {
                float4 kv = *(const float4*)&sKt[(d0 + t) * KT + c0];
                float bvals[4] = {kv.x, kv.y, kv.z, kv.w};
                #pragma unroll
                for (int i = 0; i < 2; i++) {
                    float a = f4get(aq[i], t);
                    #pragma unroll
                    for (int j = 0; j < 4; j++) accS[i][j] += a * bvals[j];
                }
            }
        }
        // scale + mask (int32 bool), write score tile to smem
        #pragma unroll
        for (int i = 0; i < 2; i++) {
            int grow = m0 + r0 + i;
            int4 mv = *(const int4*)&mask[(size_t)(b * SS + grow) * SS + n0 + c0];
            float4 o;
            o.x = mv.x ? -1e9f : accS[i][0] * 0.125f;
            o.y = mv.y ? -1e9f : accS[i][1] * 0.125f;
            o.z = mv.z ? -1e9f : accS[i][2] * 0.125f;
            o.w = mv.w ? -1e9f : accS[i][3] * 0.125f;
            *(float4*)&sS[(r0 + i) * SPAD + c0] = o;
        }
        __syncthreads();

        // Online softmax: 4 threads per row (8 cols each), shfl_xor reduction
        {
            const int rr = tid >> 2, qq = tid & 3;
            float* srow = &sS[rr * SPAD + qq * 8];
            float mloc = -1e30f;
            #pragma unroll
            for (int k = 0; k < 8; k++) mloc = fmaxf(mloc, srow[k]);
            mloc = fmaxf(mloc, __shfl_xor_sync(0xffffffffu, mloc, 1));
            mloc = fmaxf(mloc, __shfl_xor_sync(0xffffffffu, mloc, 2));
            float mold = sMx[rr];
            float mnew = fmaxf(mold, mloc);
            float corr = __expf(mold - mnew);
            float ls = 0.f;
            #pragma unroll
            for (int k = 0; k < 8; k++) {
                float p = __expf(srow[k] - mnew);
                srow[k] = p;
                ls += p;
            }
            ls += __shfl_xor_sync(0xffffffffu, ls, 1);
            ls += __shfl_xor_sync(0xffffffffu, ls, 2);
            __syncwarp();
            if (qq == 0) {
                sMx[rr] = mnew;
                sL[rr] = sL[rr] * corr + ls;
                sC[rr] = corr;
            }
        }
        __syncthreads();

        // O = corr*O + P @ V  (4x4 per thread)
        #pragma unroll
        for (int i = 0; i < 4; i++) {
            float c = sC[(ty << 2) + i];
            #pragma unroll
            for (int j = 0; j < 4; j++) acc[i][j] *= c;
        }
        #pragma unroll
        for (int nn = 0; nn < KT; nn += 4) {
            float4 p4[4];
            #pragma unroll
            for (int i = 0; i < 4; i++)
                p4[i] = *(const float4*)&sS[((ty << 2) + i) * SPAD + nn];
            #pragma unroll
            for (int t = 0; t < 4; t++) {
                float4 v4 = *(const float4*)&sV[(nn + t) * 64 + (tx << 2)];
                float vv[4] = {v4.x, v4.y, v4.z, v4.w};
                #pragma unroll
                for (int i = 0; i < 4; i++) {
                    float p = f4get(p4[i], t);
                    #pragma unroll
                    for (int j = 0; j < 4; j++) acc[i][j] += p * vv[j];
                }
            }
        }
    }

    // Epilogue: divide by l, apply row_keep = !mask[b,row,0], write [B,S,H]
    #pragma unroll
    for (int i = 0; i < 4; i++) {
        int grow = m0 + (ty << 2) + i;
        float keep = mask[(size_t)(b * SS + grow) * SS] ? 0.f : 1.f;
        float inv = keep / sL[(ty << 2) + i];
        float4 o;
        o.x = acc[i][0] * inv;
        o.y = acc[i][1] * inv;
        o.z = acc[i][2] * inv;
        o.w = acc[i][3] * inv;
        *(float4*)&out[(size_t)(b * SS + grow) * HH + h * DKH + (tx << 2)] = o;
    }
}

// ---------------------------------------------------------------------------
extern "C" void kernel_launch(void* const* d_in, const int* in_sizes, int n_in,
                              void* d_out, int out_size)
{
    const float* query  = (const float*)d_in[0];
    const float* key_in = (const float*)d_in[1];
    const int*   mask   = (const int*)d_in[2];
    const float* Wq     = (const float*)d_in[3];
    const float* bq     = (const float*)d_in[4];
    const float* Wk     = (const float*)d_in[5];
    const float* bk     = (const float*)d_in[6];
    const float* Wp     = (const float*)d_in[7];
    const float* bp     = (const float*)d_in[8];
    float* out = (float*)d_out;

    float *qp, *kp, *ap;
    cudaGetSymbolAddress((void**)&qp, g_q);
    cudaGetSymbolAddress((void**)&kp, g_k);
    cudaGetSymbolAddress((void**)&ap, g_attn);

    const int M = BB * SS, N = HH, K = HH;
    dim3 ggrid(N / 64, M / 64);

    sgemm_bias_kernel<<<ggrid, 256>>>(query, Wq, bq, qp, M, N, K);
    sgemm_bias_kernel<<<ggrid, 256>>>(key_in, Wk, bk, kp, M, N, K);

    attn_kernel<<<dim3(SS / 64, NHEADS, BB), 256>>>(qp, kp, mask, ap);

    sgemm_bias_kernel<<<ggrid, 256>>>(ap, Wp, bp, out, M, N, K);
}

// round 7
// speedup vs baseline: 1.5037x; 1.5037x over previous
#include <cuda_runtime.h>
#include <cuda_bf16.h>
#include <cstdint>

#define BB 4
#define SS 1024
#define HH 1024
#define NHEADS 16
#define DKH 64

// Scratch: q-projection, k-projection, attention output (pre final GEMM)
__device__ float g_q[BB * SS * HH];
__device__ float g_k[BB * SS * HH];
__device__ float g_attn[BB * SS * HH];

__device__ __forceinline__ float f4get(const float4& v, int t) {
    switch (t) { case 0: return v.x; case 1: return v.y; case 2: return v.z; default: return v.w; }
}

// ===========================================================================
// bf16-split tensor-core GEMM:  C[M,N] = A[M,K] @ W[K,N] + bias[N]
// fp32 emulated as hi+lo bf16: A*B ~= Ah*Bh + Ah*Bl + Al*Bh  (err ~1e-5)
// Tile 128x64x32, 256 thr, 8 warps (4x2), warp tile 32x32, mma.m16n8k16.
// ===========================================================================
#define GBM 128
#define GBN 64
#define GBK 32
#define ASTR (GBK + 8)   // 40 bf16 = 80B row stride (16B-aligned, conflict-free)
#define BSTR (GBN + 8)   // 72 bf16 = 144B row stride

__device__ __forceinline__ uint32_t smem_u32(const void* p) {
    return (uint32_t)__cvta_generic_to_shared(p);
}
__device__ __forceinline__ void ldmat_x4(uint32_t* r, uint32_t addr) {
    asm volatile("ldmatrix.sync.aligned.m8n8.x4.shared.b16 {%0,%1,%2,%3}, [%4];"
        : "=r"(r[0]), "=r"(r[1]), "=r"(r[2]), "=r"(r[3]) : "r"(addr));
}
__device__ __forceinline__ void ldmat_x4_t(uint32_t* r, uint32_t addr) {
    asm volatile("ldmatrix.sync.aligned.m8n8.x4.trans.shared.b16 {%0,%1,%2,%3}, [%4];"
        : "=r"(r[0]), "=r"(r[1]), "=r"(r[2]), "=r"(r[3]) : "r"(addr));
}
__device__ __forceinline__ void mma_bf16(float (&d)[4], const uint32_t* a, const uint32_t* b) {
    asm volatile("mma.sync.aligned.m16n8k16.row.col.f32.bf16.bf16.f32 "
        "{%0,%1,%2,%3}, {%4,%5,%6,%7}, {%8,%9}, {%0,%1,%2,%3};"
        : "+f"(d[0]), "+f"(d[1]), "+f"(d[2]), "+f"(d[3])
        : "r"(a[0]), "r"(a[1]), "r"(a[2]), "r"(a[3]), "r"(b[0]), "r"(b[1]));
}
__device__ __forceinline__ __nv_bfloat162 split_hi(float x0, float x1, __nv_bfloat162& lo) {
    __nv_bfloat16 h0 = __float2bfloat16(x0);
    __nv_bfloat16 h1 = __float2bfloat16(x1);
    lo.x = __float2bfloat16(x0 - __bfloat162float(h0));
    lo.y = __float2bfloat16(x1 - __bfloat162float(h1));
    __nv_bfloat162 hi; hi.x = h0; hi.y = h1;
    return hi;
}

__global__ __launch_bounds__(256) void gemm_mma_bias(
    const float* __restrict__ A, const float* __restrict__ W,
    const float* __restrict__ bias, float* __restrict__ C,
    int M, int N, int K)
{
    __shared__ __nv_bfloat16 Ah[GBM][ASTR];
    __shared__ __nv_bfloat16 Al[GBM][ASTR];
    __shared__ __nv_bfloat16 Bh[GBK][BSTR];
    __shared__ __nv_bfloat16 Bl[GBK][BSTR];

    const int tid = threadIdx.x;
    const int wid = tid >> 5, lane = tid & 31;
    const int m0 = blockIdx.y * GBM, n0 = blockIdx.x * GBN;
    const int wm = (wid & 3) << 5;   // warp m base: 0/32/64/96
    const int wn = (wid >> 2) << 5;  // warp n base: 0/32

    float d[2][4][4];
    #pragma unroll
    for (int mf = 0; mf < 2; mf++)
        #pragma unroll
        for (int nf = 0; nf < 4; nf++)
            #pragma unroll
            for (int r = 0; r < 4; r++) d[mf][nf][r] = 0.f;

    // gmem load indices: A tile 128x32 (4 float4/thr), B tile 32x64 (2 float4/thr)
    const int ar = tid >> 3;          // 0..31 (+32*i)
    const int ac = (tid & 7) << 2;    // 0..28
    const int br = tid >> 4;          // 0..15 (+16*i)
    const int bc = (tid & 15) << 2;   // 0..60

    const float* Abase = A + (size_t)(m0 + ar) * K + ac;
    const float* Wbase = W + (size_t)br * N + n0 + bc;

    float4 av[4], bv[2];
    #pragma unroll
    for (int i = 0; i < 4; i++) av[i] = *(const float4*)(Abase + (size_t)(32 * i) * K);
    #pragma unroll
    for (int i = 0; i < 2; i++) bv[i] = *(const float4*)(Wbase + (size_t)(16 * i) * N);

    for (int k0 = 0; k0 < K; k0 += GBK) {
        __syncthreads();   // previous compute done before smem overwrite
        // convert + store current tile
        #pragma unroll
        for (int i = 0; i < 4; i++) {
            __nv_bfloat162 lo0, lo1;
            __nv_bfloat162 hi0 = split_hi(av[i].x, av[i].y, lo0);
            __nv_bfloat162 hi1 = split_hi(av[i].z, av[i].w, lo1);
            *(__nv_bfloat162*)&Ah[ar + 32 * i][ac]     = hi0;
            *(__nv_bfloat162*)&Ah[ar + 32 * i][ac + 2] = hi1;
            *(__nv_bfloat162*)&Al[ar + 32 * i][ac]     = lo0;
            *(__nv_bfloat162*)&Al[ar + 32 * i][ac + 2] = lo1;
        }
        #pragma unroll
        for (int i = 0; i < 2; i++) {
            __nv_bfloat162 lo0, lo1;
            __nv_bfloat162 hi0 = split_hi(bv[i].x, bv[i].y, lo0);
            __nv_bfloat162 hi1 = split_hi(bv[i].z, bv[i].w, lo1);
            *(__nv_bfloat162*)&Bh[br + 16 * i][bc]     = hi0;
            *(__nv_bfloat162*)&Bh[br + 16 * i][bc + 2] = hi1;
            *(__nv_bfloat162*)&Bl[br + 16 * i][bc]     = lo0;
            *(__nv_bfloat162*)&Bl[br + 16 * i][bc + 2] = lo1;
        }
        __syncthreads();

        // prefetch next tile into registers (overlaps with mma work)
        int kn = k0 + GBK;
        if (kn < K) {
            #pragma unroll
            for (int i = 0; i < 4; i++)
                av[i] = *(const float4*)(Abase + (size_t)(32 * i) * K + kn);
            #pragma unroll
            for (int i = 0; i < 2; i++)
                bv[i] = *(const float4*)(Wbase + (size_t)(16 * i) * N + (size_t)kn * N);
        }

        // compute: two k16 sub-steps
        #pragma unroll
        for (int kk = 0; kk < GBK; kk += 16) {
            uint32_t ahf[2][4], alf[2][4], bhf[2][4], blf[2][4];
            #pragma unroll
            for (int mf = 0; mf < 2; mf++) {
                int row = wm + mf * 16 + (lane & 15);
                int col = kk + ((lane >> 4) << 3);
                ldmat_x4(ahf[mf], smem_u32(&Ah[row][col]));
                ldmat_x4(alf[mf], smem_u32(&Al[row][col]));
            }
            #pragma unroll
            for (int nf2 = 0; nf2 < 2; nf2++) {
                int row = kk + (lane & 15);
                int col = wn + nf2 * 16 + ((lane >> 4) << 3);
                ldmat_x4_t(bhf[nf2], smem_u32(&Bh[row][col]));
                ldmat_x4_t(blf[nf2], smem_u32(&Bl[row][col]));
            }
            #pragma unroll
            for (int mf = 0; mf < 2; mf++)
                #pragma unroll
                for (int nf = 0; nf < 4; nf++) {
                    const uint32_t* bh = &bhf[nf >> 1][(nf & 1) << 1];
                    const uint32_t* bl = &blf[nf >> 1][(nf & 1) << 1];
                    mma_bf16(d[mf][nf], ahf[mf], bh);
                    mma_bf16(d[mf][nf], ahf[mf], bl);
                    mma_bf16(d[mf][nf], alf[mf], bh);
                }
        }
    }

    // epilogue: D layout m16n8 -> lane holds (row=lane>>2, col=(lane&3)*2) and row+8
    #pragma unroll
    for (int mf = 0; mf < 2; mf++) {
        int row = m0 + wm + mf * 16 + (lane >> 2);
        #pragma unroll
        for (int nf = 0; nf < 4; nf++) {
            int col = n0 + wn + nf * 8 + ((lane & 3) << 1);
            float2 bb = *(const float2*)&bias[col];
            float2 v0 = make_float2(d[mf][nf][0] + bb.x, d[mf][nf][1] + bb.y);
            float2 v1 = make_float2(d[mf][nf][2] + bb.x, d[mf][nf][3] + bb.y);
            *(float2*)&C[(size_t)row * N + col] = v0;
            *(float2*)&C[(size_t)(row + 8) * N + col] = v1;
        }
    }
}

// ---------------------------------------------------------------------------
// Fused attention: per (b, h, 64-row q tile); streams 32-row K/V tiles with
// online softmax. V = q-projection. Mask is int32 (bool->int32): nonzero =
// masked (-1e9); row_keep multiplies row by !mask[b,row,0].
// ---------------------------------------------------------------------------
#define KT 32
#define SPAD 36

__global__ __launch_bounds__(256) void attn_kernel(
    const float* __restrict__ qp, const float* __restrict__ kp,
    const int* __restrict__ mask, float* __restrict__ out)
{
    __shared__ float sQ[64 * 64];
    __shared__ float sKt[64 * KT];
    __shared__ float sV[KT * 64];
    __shared__ float sS[64 * SPAD];
    __shared__ float sMx[64];
    __shared__ float sL[64];
    __shared__ float sC[64];

    const int tid = threadIdx.x;
    const int tx = tid & 15, ty = tid >> 4;
    const int b = blockIdx.z, h = blockIdx.y;
    const int m0 = blockIdx.x * 64;

    {
        const int lr = tid >> 2;
        const int ld0 = (tid & 3) << 4;
        const float* src = qp + (size_t)(b * SS + m0 + lr) * HH + h * DKH + ld0;
        #pragma unroll
        for (int i = 0; i < 4; i++)
            *(float4*)&sQ[lr * 64 + ld0 + 4 * i] = *(const float4*)(src + 4 * i);
    }
    if (tid < 64) { sMx[tid] = -1e30f; sL[tid] = 0.f; }

    float acc[4][4] = {};

    const int lr2 = tid >> 3;
    const int ld2 = (tid & 7) << 3;
    const int r0 = (tid >> 3) << 1;
    const int c0 = (tid & 7) << 2;

    for (int n0 = 0; n0 < SS; n0 += KT) {
        __syncthreads();
        {
            const float* ksrc = kp + (size_t)(b * SS + n0 + lr2) * HH + h * DKH + ld2;
            const float* vsrc = qp + (size_t)(b * SS + n0 + lr2) * HH + h * DKH + ld2;
            #pragma unroll
            for (int i = 0; i < 2; i++) {
                float4 kv = *(const float4*)(ksrc + 4 * i);
                int dd = ld2 + 4 * i;
                sKt[(dd + 0) * KT + lr2] = kv.x;
                sKt[(dd + 1) * KT + lr2] = kv.y;
                sKt[(dd + 2) * KT + lr2] = kv.z;
                sKt[(dd + 3) * KT + lr2] = kv.w;
                *(float4*)&sV[lr2 * 64 + dd] = *(const float4*)(vsrc + 4 * i);
            }
        }
        __syncthreads();

        float accS[2][4] = {};
        #pragma unroll
        for (int d0 = 0; d0 < 64; d0 += 4) {
            float4 aq[2];
            aq[0] = *(const float4*)&sQ[(r0 + 0) * 64 + d0];
            aq[1] = *(const float4*)&sQ[(r0 + 1) * 64 + d0];
            #pragma unroll
            for (int t = 0; t < 4; t++) {
                float4 kv = *(const float4*)&sKt[(d0 + t) * KT + c0];
                float bvals[4] = {kv.x, kv.y, kv.z, kv.w};
                #pragma unroll
                for (int i = 0; i < 2; i++) {
                    float a = f4get(aq[i], t);
                    #pragma unroll
                    for (int j = 0; j < 4; j++) accS[i][j] += a * bvals[j];
                }
            }
        }
        #pragma unroll
        for (int i = 0; i < 2; i++) {
            int grow = m0 + r0 + i;
            int4 mv = *(const int4*)&mask[(size_t)(b * SS + grow) * SS + n0 + c0];
            float4 o;
            o.x = mv.x ? -1e9f : accS[i][0] * 0.125f;
            o.y = mv.y ? -1e9f : accS[i][1] * 0.125f;
            o.z = mv.z ? -1e9f : accS[i][2] * 0.125f;
            o.w = mv.w ? -1e9f : accS[i][3] * 0.125f;
            *(float4*)&sS[(r0 + i) * SPAD + c0] = o;
        }
        __syncthreads();

        {
            const int rr = tid >> 2, qq = tid & 3;
            float* srow = &sS[rr * SPAD + qq * 8];
            float mloc = -1e30f;
            #pragma unroll
            for (int k = 0; k < 8; k++) mloc = fmaxf(mloc, srow[k]);
            mloc = fmaxf(mloc, __shfl_xor_sync(0xffffffffu, mloc, 1));
            mloc = fmaxf(mloc, __shfl_xor_sync(0xffffffffu, mloc, 2));
            float mold = sMx[rr];
            float mnew = fmaxf(mold, mloc);
            float corr = __expf(mold - mnew);
            float ls = 0.f;
            #pragma unroll
            for (int k = 0; k < 8; k++) {
                float p = __expf(srow[k] - mnew);
                srow[k] = p;
                ls += p;
            }
            ls += __shfl_xor_sync(0xffffffffu, ls, 1);
            ls += __shfl_xor_sync(0xffffffffu, ls, 2);
            __syncwarp();
            if (qq == 0) {
                sMx[rr] = mnew;
                sL[rr] = sL[rr] * corr + ls;
                sC[rr] = corr;
            }
        }
        __syncthreads();

        #pragma unroll
        for (int i = 0; i < 4; i++) {
            float c = sC[(ty << 2) + i];
            #pragma unroll
            for (int j = 0; j < 4; j++) acc[i][j] *= c;
        }
        #pragma unroll
        for (int nn = 0; nn < KT; nn += 4) {
            float4 p4[4];
            #pragma unroll
            for (int i = 0; i < 4; i++)
                p4[i] = *(const float4*)&sS[((ty << 2) + i) * SPAD + nn];
            #pragma unroll
            for (int t = 0; t < 4; t++) {
                float4 v4 = *(const float4*)&sV[(nn + t) * 64 + (tx << 2)];
                float vv[4] = {v4.x, v4.y, v4.z, v4.w};
                #pragma unroll
                for (int i = 0; i < 4; i++) {
                    float p = f4get(p4[i], t);
                    #pragma unroll
                    for (int j = 0; j < 4; j++) acc[i][j] += p * vv[j];
                }
            }
        }
    }

    #pragma unroll
    for (int i = 0; i < 4; i++) {
        int grow = m0 + (ty << 2) + i;
        float keep = mask[(size_t)(b * SS + grow) * SS] ? 0.f : 1.f;
        float inv = keep / sL[(ty << 2) + i];
        float4 o;
        o.x = acc[i][0] * inv;
        o.y = acc[i][1] * inv;
        o.z = acc[i][2] * inv;
        o.w = acc[i][3] * inv;
        *(float4*)&out[(size_t)(b * SS + grow) * HH + h * DKH + (tx << 2)] = o;
    }
}

// ---------------------------------------------------------------------------
extern "C" void kernel_launch(void* const* d_in, const int* in_sizes, int n_in,
                              void* d_out, int out_size)
{
    const float* query  = (const float*)d_in[0];
    const float* key_in = (const float*)d_in[1];
    const int*   mask   = (const int*)d_in[2];
    const float* Wq     = (const float*)d_in[3];
    const float* bq     = (const float*)d_in[4];
    const float* Wk     = (const float*)d_in[5];
    const float* bk     = (const float*)d_in[6];
    const float* Wp     = (const float*)d_in[7];
    const float* bp     = (const float*)d_in[8];
    float* out = (float*)d_out;

    float *qp, *kp, *ap;
    cudaGetSymbolAddress((void**)&qp, g_q);
    cudaGetSymbolAddress((void**)&kp, g_k);
    cudaGetSymbolAddress((void**)&ap, g_attn);

    const int M = BB * SS, N = HH, K = HH;
    dim3 ggrid(N / GBN, M / GBM);   // (16, 32)

    gemm_mma_bias<<<ggrid, 256>>>(query, Wq, bq, qp, M, N, K);
    gemm_mma_bias<<<ggrid, 256>>>(key_in, Wk, bk, kp, M, N, K);

    attn_kernel<<<dim3(SS / 64, NHEADS, BB), 256>>>(qp, kp, mask, ap);

    gemm_mma_bias<<<ggrid, 256>>>(ap, Wp, bp, out, M, N, K);
}

// round 8
// speedup vs baseline: 2.7582x; 1.8343x over previous
#include <cuda_runtime.h>
#include <cuda_bf16.h>
#include <cstdint>

#define BB 4
#define SS 1024
#define HH 1024
#define NHEADS 16
#define DKH 64

// Scratch: q-projection, k-projection, attention output (pre final GEMM)
__device__ float g_q[BB * SS * HH];
__device__ float g_k[BB * SS * HH];
__device__ float g_attn[BB * SS * HH];

// ===========================================================================
// Common MMA helpers (bf16 split precision)
// ===========================================================================
__device__ __forceinline__ uint32_t smem_u32(const void* p) {
    return (uint32_t)__cvta_generic_to_shared(p);
}
__device__ __forceinline__ void ldmat_x4(uint32_t* r, uint32_t addr) {
    asm volatile("ldmatrix.sync.aligned.m8n8.x4.shared.b16 {%0,%1,%2,%3}, [%4];"
        : "=r"(r[0]), "=r"(r[1]), "=r"(r[2]), "=r"(r[3]) : "r"(addr));
}
__device__ __forceinline__ void ldmat_x4_t(uint32_t* r, uint32_t addr) {
    asm volatile("ldmatrix.sync.aligned.m8n8.x4.trans.shared.b16 {%0,%1,%2,%3}, [%4];"
        : "=r"(r[0]), "=r"(r[1]), "=r"(r[2]), "=r"(r[3]) : "r"(addr));
}
__device__ __forceinline__ void mma_bf16(float (&d)[4], const uint32_t* a,
                                         uint32_t b0, uint32_t b1) {
    asm volatile("mma.sync.aligned.m16n8k16.row.col.f32.bf16.bf16.f32 "
        "{%0,%1,%2,%3}, {%4,%5,%6,%7}, {%8,%9}, {%0,%1,%2,%3};"
        : "+f"(d[0]), "+f"(d[1]), "+f"(d[2]), "+f"(d[3])
        : "r"(a[0]), "r"(a[1]), "r"(a[2]), "r"(a[3]), "r"(b0), "r"(b1));
}
__device__ __forceinline__ __nv_bfloat162 split_hi(float x0, float x1, __nv_bfloat162& lo) {
    __nv_bfloat16 h0 = __float2bfloat16(x0);
    __nv_bfloat16 h1 = __float2bfloat16(x1);
    lo.x = __float2bfloat16(x0 - __bfloat162float(h0));
    lo.y = __float2bfloat16(x1 - __bfloat162float(h1));
    __nv_bfloat162 hi; hi.x = h0; hi.y = h1;
    return hi;
}
__device__ __forceinline__ uint32_t bf2_u32(__nv_bfloat162 v) {
    return *(uint32_t*)&v;
}

// ===========================================================================
// bf16-split tensor-core GEMM:  C[M,N] = A[M,K] @ W[K,N] + bias[N]
// Tile 128x64x32, 256 thr, 8 warps (4x2), warp tile 32x32, mma.m16n8k16.
// ===========================================================================
#define GBM 128
#define GBN 64
#define GBK 32
#define ASTR (GBK + 8)
#define BSTR (GBN + 8)

__global__ __launch_bounds__(256) void gemm_mma_bias(
    const float* __restrict__ A, const float* __restrict__ W,
    const float* __restrict__ bias, float* __restrict__ C,
    int M, int N, int K)
{
    __shared__ __nv_bfloat16 Ah[GBM][ASTR];
    __shared__ __nv_bfloat16 Al[GBM][ASTR];
    __shared__ __nv_bfloat16 Bh[GBK][BSTR];
    __shared__ __nv_bfloat16 Bl[GBK][BSTR];

    const int tid = threadIdx.x;
    const int wid = tid >> 5, lane = tid & 31;
    const int m0 = blockIdx.y * GBM, n0 = blockIdx.x * GBN;
    const int wm = (wid & 3) << 5;
    const int wn = (wid >> 2) << 5;

    float d[2][4][4];
    #pragma unroll
    for (int mf = 0; mf < 2; mf++)
        #pragma unroll
        for (int nf = 0; nf < 4; nf++)
            #pragma unroll
            for (int r = 0; r < 4; r++) d[mf][nf][r] = 0.f;

    const int ar = tid >> 3;
    const int ac = (tid & 7) << 2;
    const int br = tid >> 4;
    const int bc = (tid & 15) << 2;

    const float* Abase = A + (size_t)(m0 + ar) * K + ac;
    const float* Wbase = W + (size_t)br * N + n0 + bc;

    float4 av[4], bv[2];
    #pragma unroll
    for (int i = 0; i < 4; i++) av[i] = *(const float4*)(Abase + (size_t)(32 * i) * K);
    #pragma unroll
    for (int i = 0; i < 2; i++) bv[i] = *(const float4*)(Wbase + (size_t)(16 * i) * N);

    for (int k0 = 0; k0 < K; k0 += GBK) {
        __syncthreads();
        #pragma unroll
        for (int i = 0; i < 4; i++) {
            __nv_bfloat162 lo0, lo1;
            __nv_bfloat162 hi0 = split_hi(av[i].x, av[i].y, lo0);
            __nv_bfloat162 hi1 = split_hi(av[i].z, av[i].w, lo1);
            *(__nv_bfloat162*)&Ah[ar + 32 * i][ac]     = hi0;
            *(__nv_bfloat162*)&Ah[ar + 32 * i][ac + 2] = hi1;
            *(__nv_bfloat162*)&Al[ar + 32 * i][ac]     = lo0;
            *(__nv_bfloat162*)&Al[ar + 32 * i][ac + 2] = lo1;
        }
        #pragma unroll
        for (int i = 0; i < 2; i++) {
            __nv_bfloat162 lo0, lo1;
            __nv_bfloat162 hi0 = split_hi(bv[i].x, bv[i].y, lo0);
            __nv_bfloat162 hi1 = split_hi(bv[i].z, bv[i].w, lo1);
            *(__nv_bfloat162*)&Bh[br + 16 * i][bc]     = hi0;
            *(__nv_bfloat162*)&Bh[br + 16 * i][bc + 2] = hi1;
            *(__nv_bfloat162*)&Bl[br + 16 * i][bc]     = lo0;
            *(__nv_bfloat162*)&Bl[br + 16 * i][bc + 2] = lo1;
        }
        __syncthreads();

        int kn = k0 + GBK;
        if (kn < K) {
            #pragma unroll
            for (int i = 0; i < 4; i++)
                av[i] = *(const float4*)(Abase + (size_t)(32 * i) * K + kn);
            #pragma unroll
            for (int i = 0; i < 2; i++)
                bv[i] = *(const float4*)(Wbase + (size_t)(16 * i) * N + (size_t)kn * N);
        }

        #pragma unroll
        for (int kk = 0; kk < GBK; kk += 16) {
            uint32_t ahf[2][4], alf[2][4], bhf[2][4], blf[2][4];
            #pragma unroll
            for (int mf = 0; mf < 2; mf++) {
                int row = wm + mf * 16 + (lane & 15);
                int col = kk + ((lane >> 4) << 3);
                ldmat_x4(ahf[mf], smem_u32(&Ah[row][col]));
                ldmat_x4(alf[mf], smem_u32(&Al[row][col]));
            }
            #pragma unroll
            for (int nf2 = 0; nf2 < 2; nf2++) {
                int row = kk + (lane & 15);
                int col = wn + nf2 * 16 + ((lane >> 4) << 3);
                ldmat_x4_t(bhf[nf2], smem_u32(&Bh[row][col]));
                ldmat_x4_t(blf[nf2], smem_u32(&Bl[row][col]));
            }
            #pragma unroll
            for (int mf = 0; mf < 2; mf++)
                #pragma unroll
                for (int nf = 0; nf < 4; nf++) {
                    uint32_t bh0 = bhf[nf >> 1][(nf & 1) << 1];
                    uint32_t bh1 = bhf[nf >> 1][((nf & 1) << 1) + 1];
                    uint32_t bl0 = blf[nf >> 1][(nf & 1) << 1];
                    uint32_t bl1 = blf[nf >> 1][((nf & 1) << 1) + 1];
                    mma_bf16(d[mf][nf], ahf[mf], bh0, bh1);
                    mma_bf16(d[mf][nf], ahf[mf], bl0, bl1);
                    mma_bf16(d[mf][nf], alf[mf], bh0, bh1);
                }
        }
    }

    #pragma unroll
    for (int mf = 0; mf < 2; mf++) {
        int row = m0 + wm + mf * 16 + (lane >> 2);
        #pragma unroll
        for (int nf = 0; nf < 4; nf++) {
            int col = n0 + wn + nf * 8 + ((lane & 3) << 1);
            float2 bb = *(const float2*)&bias[col];
            float2 v0 = make_float2(d[mf][nf][0] + bb.x, d[mf][nf][1] + bb.y);
            float2 v1 = make_float2(d[mf][nf][2] + bb.x, d[mf][nf][3] + bb.y);
            *(float2*)&C[(size_t)row * N + col] = v0;
            *(float2*)&C[(size_t)(row + 8) * N + col] = v1;
        }
    }
}

// ===========================================================================
// FA2-style tensor-core attention, bf16-split (3-pass) for QK^T and PV.
// Block: 128 q rows x (b,h). 8 warps, each an m16 slab. KV tile = 64.
// S lives in registers; online softmax; V = q-projection.
// ===========================================================================
#define QT 128
#define KVT 64
#define QSTR 72   // 144B row stride: 16B-aligned, ldmatrix conflict-free

__global__ __launch_bounds__(256) void attn_mma_kernel(
    const float* __restrict__ qp, const float* __restrict__ kp,
    const int* __restrict__ mask, float* __restrict__ out)
{
    __shared__ __nv_bfloat16 sbuf[2 * 128 * QSTR];   // 36,864 B, reused Q -> K/V

    const int tid = threadIdx.x;
    const int wid = tid >> 5, lane = tid & 31;
    const int b = blockIdx.z, h = blockIdx.y;
    const int m0 = blockIdx.x * QT;
    const int warpM = wid << 4;

    // ---- Phase 1: load Q tile (128x64), convert to hi/lo bf16 in smem ----
    {
        __nv_bfloat16* Qh = sbuf;
        __nv_bfloat16* Ql = sbuf + 128 * QSTR;
        int row = tid >> 1;
        int dbase = (tid & 1) << 5;
        const float* src = qp + (size_t)(b * SS + m0 + row) * HH + h * DKH + dbase;
        #pragma unroll
        for (int i = 0; i < 8; i++) {
            float4 v = *(const float4*)(src + 4 * i);
            __nv_bfloat162 lo0, lo1;
            __nv_bfloat162 hi0 = split_hi(v.x, v.y, lo0);
            __nv_bfloat162 hi1 = split_hi(v.z, v.w, lo1);
            *(__nv_bfloat162*)&Qh[row * QSTR + dbase + 4 * i]     = hi0;
            *(__nv_bfloat162*)&Qh[row * QSTR + dbase + 4 * i + 2] = hi1;
            *(__nv_bfloat162*)&Ql[row * QSTR + dbase + 4 * i]     = lo0;
            *(__nv_bfloat162*)&Ql[row * QSTR + dbase + 4 * i + 2] = lo1;
        }
    }
    __syncthreads();

    // ---- hoist Q fragments to registers (4 k-chunks of 16) ----
    uint32_t qh[4][4], ql[4][4];
    {
        __nv_bfloat16* Qh = sbuf;
        __nv_bfloat16* Ql = sbuf + 128 * QSTR;
        #pragma unroll
        for (int kc = 0; kc < 4; kc++) {
            int row = warpM + (lane & 15);
            int col = (kc << 4) + ((lane >> 4) << 3);
            ldmat_x4(qh[kc], smem_u32(&Qh[row * QSTR + col]));
            ldmat_x4(ql[kc], smem_u32(&Ql[row * QSTR + col]));
        }
    }

    __nv_bfloat16* Kh = sbuf;
    __nv_bfloat16* Kl = sbuf + 64 * QSTR;
    __nv_bfloat16* Vh = sbuf + 2 * 64 * QSTR;
    __nv_bfloat16* Vl = sbuf + 3 * 64 * QSTR;

    float oacc[8][4];
    #pragma unroll
    for (int nf = 0; nf < 8; nf++)
        #pragma unroll
        for (int r = 0; r < 4; r++) oacc[nf][r] = 0.f;
    float mrun0 = -1e30f, mrun1 = -1e30f, lrun0 = 0.f, lrun1 = 0.f;

    const int fr = lane >> 2;          // fragment rows fr and fr+8
    const int cofs = (lane & 3) << 1;  // fragment col pair offset

    for (int n0 = 0; n0 < SS; n0 += KVT) {
        __syncthreads();   // previous tile's reads done before overwrite
        // ---- load K/V tile (64x64 each), convert hi/lo ----
        {
            int row = tid >> 2;
            int dbase = (tid & 3) << 4;
            const float* ksrc = kp + (size_t)(b * SS + n0 + row) * HH + h * DKH + dbase;
            const float* vsrc = qp + (size_t)(b * SS + n0 + row) * HH + h * DKH + dbase;
            #pragma unroll
            for (int i = 0; i < 4; i++) {
                float4 v = *(const float4*)(ksrc + 4 * i);
                __nv_bfloat162 lo0, lo1;
                __nv_bfloat162 hi0 = split_hi(v.x, v.y, lo0);
                __nv_bfloat162 hi1 = split_hi(v.z, v.w, lo1);
                *(__nv_bfloat162*)&Kh[row * QSTR + dbase + 4 * i]     = hi0;
                *(__nv_bfloat162*)&Kh[row * QSTR + dbase + 4 * i + 2] = hi1;
                *(__nv_bfloat162*)&Kl[row * QSTR + dbase + 4 * i]     = lo0;
                *(__nv_bfloat162*)&Kl[row * QSTR + dbase + 4 * i + 2] = lo1;
                v = *(const float4*)(vsrc + 4 * i);
                hi0 = split_hi(v.x, v.y, lo0);
                hi1 = split_hi(v.z, v.w, lo1);
                *(__nv_bfloat162*)&Vh[row * QSTR + dbase + 4 * i]     = hi0;
                *(__nv_bfloat162*)&Vh[row * QSTR + dbase + 4 * i + 2] = hi1;
                *(__nv_bfloat162*)&Vl[row * QSTR + dbase + 4 * i]     = lo0;
                *(__nv_bfloat162*)&Vl[row * QSTR + dbase + 4 * i + 2] = lo1;
            }
        }
        __syncthreads();

        // ---- S = Q @ K^T (K is [kv][d] = col-major kxn -> non-trans ldmatrix) ----
        float sacc[8][4];
        #pragma unroll
        for (int nf = 0; nf < 8; nf++)
            #pragma unroll
            for (int r = 0; r < 4; r++) sacc[nf][r] = 0.f;

        #pragma unroll
        for (int kc = 0; kc < 4; kc++) {
            #pragma unroll
            for (int t = 0; t < 4; t++) {
                uint32_t kh[4], kl[4];
                int row = (t << 4) + (lane & 15);
                int col = (kc << 4) + ((lane >> 4) << 3);
                ldmat_x4(kh, smem_u32(&Kh[row * QSTR + col]));
                ldmat_x4(kl, smem_u32(&Kl[row * QSTR + col]));
                // n-group 0 of this tile: b = {kh[0], kh[2]}; group 1: {kh[1], kh[3]}
                mma_bf16(sacc[2 * t], qh[kc], kh[0], kh[2]);
                mma_bf16(sacc[2 * t], qh[kc], kl[0], kl[2]);
                mma_bf16(sacc[2 * t], ql[kc], kh[0], kh[2]);
                mma_bf16(sacc[2 * t + 1], qh[kc], kh[1], kh[3]);
                mma_bf16(sacc[2 * t + 1], qh[kc], kl[1], kl[3]);
                mma_bf16(sacc[2 * t + 1], ql[kc], kh[1], kh[3]);
            }
        }

        // ---- scale + mask + online softmax (register fragments) ----
        const int* mp0 = mask + (size_t)(b * SS + m0 + warpM + fr) * SS + n0 + cofs;
        const int* mp1 = mp0 + (size_t)8 * SS;
        float mloc0 = -3e38f, mloc1 = -3e38f;
        #pragma unroll
        for (int nf = 0; nf < 8; nf++) {
            int2 mv0 = *(const int2*)(mp0 + nf * 8);
            int2 mv1 = *(const int2*)(mp1 + nf * 8);
            sacc[nf][0] = mv0.x ? -1e9f : sacc[nf][0] * 0.125f;
            sacc[nf][1] = mv0.y ? -1e9f : sacc[nf][1] * 0.125f;
            sacc[nf][2] = mv1.x ? -1e9f : sacc[nf][2] * 0.125f;
            sacc[nf][3] = mv1.y ? -1e9f : sacc[nf][3] * 0.125f;
            mloc0 = fmaxf(mloc0, fmaxf(sacc[nf][0], sacc[nf][1]));
            mloc1 = fmaxf(mloc1, fmaxf(sacc[nf][2], sacc[nf][3]));
        }
        mloc0 = fmaxf(mloc0, __shfl_xor_sync(0xffffffffu, mloc0, 1));
        mloc0 = fmaxf(mloc0, __shfl_xor_sync(0xffffffffu, mloc0, 2));
        mloc1 = fmaxf(mloc1, __shfl_xor_sync(0xffffffffu, mloc1, 1));
        mloc1 = fmaxf(mloc1, __shfl_xor_sync(0xffffffffu, mloc1, 2));

        float mnew0 = fmaxf(mrun0, mloc0), mnew1 = fmaxf(mrun1, mloc1);
        float corr0 = __expf(mrun0 - mnew0), corr1 = __expf(mrun1 - mnew1);
        mrun0 = mnew0; mrun1 = mnew1;

        float ls0 = 0.f, ls1 = 0.f;
        #pragma unroll
        for (int nf = 0; nf < 8; nf++) {
            sacc[nf][0] = __expf(sacc[nf][0] - mnew0);
            sacc[nf][1] = __expf(sacc[nf][1] - mnew0);
            sacc[nf][2] = __expf(sacc[nf][2] - mnew1);
            sacc[nf][3] = __expf(sacc[nf][3] - mnew1);
            ls0 += sacc[nf][0] + sacc[nf][1];
            ls1 += sacc[nf][2] + sacc[nf][3];
        }
        ls0 += __shfl_xor_sync(0xffffffffu, ls0, 1);
        ls0 += __shfl_xor_sync(0xffffffffu, ls0, 2);
        ls1 += __shfl_xor_sync(0xffffffffu, ls1, 1);
        ls1 += __shfl_xor_sync(0xffffffffu, ls1, 2);
        lrun0 = lrun0 * corr0 + ls0;
        lrun1 = lrun1 * corr1 + ls1;

        #pragma unroll
        for (int nf = 0; nf < 8; nf++) {
            oacc[nf][0] *= corr0; oacc[nf][1] *= corr0;
            oacc[nf][2] *= corr1; oacc[nf][3] *= corr1;
        }

        // ---- convert P to hi/lo bf16x2 A-fragments (no smem round-trip) ----
        uint32_t pha[8], phb[8], pla[8], plb[8];
        #pragma unroll
        for (int nf = 0; nf < 8; nf++) {
            __nv_bfloat162 lo;
            __nv_bfloat162 hi = split_hi(sacc[nf][0], sacc[nf][1], lo);
            pha[nf] = bf2_u32(hi); pla[nf] = bf2_u32(lo);
            hi = split_hi(sacc[nf][2], sacc[nf][3], lo);
            phb[nf] = bf2_u32(hi); plb[nf] = bf2_u32(lo);
        }

        // ---- O += P @ V (V is [kv][d] row-major kxn -> trans ldmatrix) ----
        #pragma unroll
        for (int j = 0; j < 4; j++) {
            uint32_t ah[4] = {pha[2 * j], phb[2 * j], pha[2 * j + 1], phb[2 * j + 1]};
            uint32_t al[4] = {pla[2 * j], plb[2 * j], pla[2 * j + 1], plb[2 * j + 1]};
            #pragma unroll
            for (int t = 0; t < 4; t++) {
                uint32_t vh[4], vl[4];
                int row = (j << 4) + (lane & 15);
                int col = (t << 4) + ((lane >> 4) << 3);
                ldmat_x4_t(vh, smem_u32(&Vh[row * QSTR + col]));
                ldmat_x4_t(vl, smem_u32(&Vl[row * QSTR + col]));
                mma_bf16(oacc[2 * t], ah, vh[0], vh[1]);
                mma_bf16(oacc[2 * t], ah, vl[0], vl[1]);
                mma_bf16(oacc[2 * t], al, vh[0], vh[1]);
                mma_bf16(oacc[2 * t + 1], ah, vh[2], vh[3]);
                mma_bf16(oacc[2 * t + 1], ah, vl[2], vl[3]);
                mma_bf16(oacc[2 * t + 1], al, vh[2], vh[3]);
            }
        }
    }

    // ---- epilogue: 1/l, row_keep, write [B,S,H] ----
    {
        int grow0 = m0 + warpM + fr;
        float keep0 = mask[(size_t)(b * SS + grow0) * SS] ? 0.f : 1.f;
        float keep1 = mask[(size_t)(b * SS + grow0 + 8) * SS] ? 0.f : 1.f;
        float inv0 = keep0 / lrun0;
        float inv1 = keep1 / lrun1;
        float* o0 = out + (size_t)(b * SS + grow0) * HH + h * DKH + cofs;
        float* o1 = o0 + (size_t)8 * HH;
        #pragma unroll
        for (int nf = 0; nf < 8; nf++) {
            *(float2*)(o0 + nf * 8) = make_float2(oacc[nf][0] * inv0, oacc[nf][1] * inv0);
            *(float2*)(o1 + nf * 8) = make_float2(oacc[nf][2] * inv1, oacc[nf][3] * inv1);
        }
    }
}

// ---------------------------------------------------------------------------
extern "C" void kernel_launch(void* const* d_in, const int* in_sizes, int n_in,
                              void* d_out, int out_size)
{
    const float* query  = (const float*)d_in[0];
    const float* key_in = (const float*)d_in[1];
    const int*   mask   = (const int*)d_in[2];
    const float* Wq     = (const float*)d_in[3];
    const float* bq     = (const float*)d_in[4];
    const float* Wk     = (const float*)d_in[5];
    const float* bk     = (const float*)d_in[6];
    const float* Wp     = (const float*)d_in[7];
    const float* bp     = (const float*)d_in[8];
    float* out = (float*)d_out;

    float *qp, *kp, *ap;
    cudaGetSymbolAddress((void**)&qp, g_q);
    cudaGetSymbolAddress((void**)&kp, g_k);
    cudaGetSymbolAddress((void**)&ap, g_attn);

    const int M = BB * SS, N = HH, K = HH;
    dim3 ggrid(N / GBN, M / GBM);   // (16, 32)

    gemm_mma_bias<<<ggrid, 256>>>(query, Wq, bq, qp, M, N, K);
    gemm_mma_bias<<<ggrid, 256>>>(key_in, Wk, bk, kp, M, N, K);

    attn_mma_kernel<<<dim3(SS / QT, NHEADS, BB), 256>>>(qp, kp, mask, ap);

    gemm_mma_bias<<<ggrid, 256>>>(ap, Wp, bp, out, M, N, K);
}